// round 16
// baseline (speedup 1.0000x reference)
#include <cuda_runtime.h>
#include <cuda_bf16.h>
#include <cuda_fp16.h>
#include <cstdint>

#define Hh    16
#define Dd    64
#define Nq    1024
#define TPAST 4096
#define TTOT  5120
#define DIMc  1024
#define MID   3072
#define KEEPM 2048
#define SC2   0.1803368801111157f   // 0.125 * log2(e): exp2-domain Q scale

#define KSB   18432            // K tile bytes (128 rows x 144B)
#define BUFB  38016            // K tile + V tile (72 x 272B)
#define ATTN_SMEM (4 * BUFB)   // 2 warp-groups x 2 buffers

// ---------------- device scratch ----------------
__device__ float g_q [Hh*Nq*Dd];
__device__ float g_kn[Hh*Nq*Dd];
__device__ float g_vn[Hh*Nq*Dd];
__device__ float g_xp[64*1024];
__device__ float g_mm[1024];
__device__ float g_sp[16*3072];
__device__ int   g_keep[KEEPM];
__device__ __half g_kb  [Hh*TTOT*Dd];   // K f16 [h][tok][d]
__device__ __half g_vtb [Hh*Dd*TTOT];   // V^T f16 [h][d][tok]
__device__ __half g_x16 [Nq*DIMc];
__device__ __half g_w16 [3072*DIMc];
__device__ __half g_pw16[DIMc*DIMc];
__device__ __half g_o16 [Nq*DIMc];      // attn out, f16 (written by attn epilogue)

// ---------------- helpers ----------------
__device__ __forceinline__ void mma_f16(float* d, const uint32_t* a, uint32_t b0, uint32_t b1) {
    asm volatile("mma.sync.aligned.m16n8k16.row.col.f32.f16.f16.f32 "
        "{%0,%1,%2,%3}, {%4,%5,%6,%7}, {%8,%9}, {%0,%1,%2,%3};"
        : "+f"(d[0]), "+f"(d[1]), "+f"(d[2]), "+f"(d[3])
        : "r"(a[0]), "r"(a[1]), "r"(a[2]), "r"(a[3]), "r"(b0), "r"(b1));
}
// exp2-domain weights: inputs pre-scaled by log2(e)
__device__ __forceinline__ uint32_t expack(float x, float y) {
    __half2 p = __floats2half2_rn(exp2f(x), exp2f(y));
    return *reinterpret_cast<uint32_t*>(&p);
}
__device__ __forceinline__ uint32_t packh(float a, float b) {
    __half2 t = __floats2half2_rn(a, b);
    return *reinterpret_cast<uint32_t*>(&t);
}
__device__ __forceinline__ void cp16(uint32_t dst, const void* src) {
    asm volatile("cp.async.cg.shared.global [%0], [%1], 16;" :: "r"(dst), "l"(src) : "memory");
}
__device__ __forceinline__ void conv_range(const float* __restrict__ s, __half* __restrict__ d, int f) {
    float4 v = *(const float4*)(s + (size_t)f * 4);
    *(uint2*)((char*)d + (size_t)f * 8) = make_uint2(packh(v.x, v.y), packh(v.z, v.w));
}

// ---------------- stage1: all input conversions + xm partials ------------
// grid 5376 x 256: [0,1024) x->x16 | [1024,4096) qkv_w->w16 |
// [4096,5120) proj_w->pw16 | [5120,5376) weighted x-row partial sums
__global__ void stage1(const float* __restrict__ x, const float* __restrict__ qkv_w,
                       const float* __restrict__ proj_w) {
    const int b = blockIdx.x, t = threadIdx.x;
    if (b < 1024) {
        conv_range(x, g_x16, b * 256 + t);
    } else if (b < 4096) {
        conv_range(qkv_w, g_w16, (b - 1024) * 256 + t);
    } else if (b < 5120) {
        conv_range(proj_w, g_pw16, (b - 4096) * 256 + t);
    } else {
        const int q = b - 5120;              // 256 blocks: 4 c-blks x 64 r-blks
        const int c = (q & 3) * 256 + t;
        const int r0 = (q >> 2) * 16;
        float acc = 0.0f;
        for (int r = r0; r < r0 + 16; r++) {
            float w = (r < 5) ? 1.0f : (r < 1013 ? (1.0f / 16.0f) : (1.0f / 11.0f));
            acc += w * x[(size_t)r * 1024 + c];
        }
        g_xp[(q >> 2) * 1024 + c] = acc;
    }
}

// ---------------- qm: xw reduce (per-block, redundant) + Wq·xw -----------
// mm[j] = Wq[j]·xw + 69*b[j]. grid 64 x 256.
__global__ void qm(const float* __restrict__ Wq, const float* __restrict__ qb) {
    __shared__ float red[256];
    __shared__ float xw[1024];
    const int t = threadIdx.x;
    for (int c = t; c < 1024; c += 256) {
        float a = 0.0f;
        #pragma unroll
        for (int i = 0; i < 64; i++) a += g_xp[i * 1024 + c];
        xw[c] = a;
    }
    __syncthreads();
    const int jl = t >> 4, part = t & 15;
    const int j = blockIdx.x * 16 + jl;
    const float* wr = Wq + (size_t)j * 1024 + part * 64;
    const float* xp = &xw[part * 64];
    float acc = 0.0f;
    #pragma unroll
    for (int cc = 0; cc < 64; cc += 4) {
        float4 v = *(const float4*)(wr + cc);
        acc += v.x * xp[cc] + v.y * xp[cc+1] + v.z * xp[cc+2] + v.w * xp[cc+3];
    }
    red[t] = acc;
    __syncthreads();
    if (part == 0) {
        float s = 0.0f;
        #pragma unroll
        for (int p = 0; p < 16; p++) s += red[jl * 16 + p];
        g_mm[j] = s + 69.0f * qb[j];
    }
}

// ---------------- mega: qkv GEMM + past-KV conversion + scores -----------
// grid 2112 x 256, roles by blockIdx.x (gemm first => scheduled first):
//   [0,384)      qkv gemm (j0 = (bx>>3)*64, n0 = (bx&7)*128), scatter epilogue
//                + direct f16 side-writes of new-token K rows / V^T columns
//   [384,896)    conv_k past: 512 = 16h x 32 tile-of-128
//   [896,1920)   conv_vt past: 1024 = 16h x 64 tile-of-64
//   [1920,2112)  scores: 192 = 16h x 12 blocks of 256 positions
__global__ void __launch_bounds__(256) mega(
    const float* __restrict__ qkv_b,
    const float* __restrict__ pk, const float* __restrict__ pv)
{
    __shared__ char shm[27648];
    const int bx = blockIdx.x, t = threadIdx.x;

    if (bx < 384) {            // ---------- gemm role ----------
        __half* As = (__half*)shm;                 // 128 x 72
        __half* Bs = (__half*)(shm + 18432);       // 64 x 72
        const int lane = t & 31, w = t >> 5;
        const int j0 = (bx >> 3) * 64, n0 = (bx & 7) * 128;
        const int g = lane >> 2, i = lane & 3;
        float acc[8][4] = {};
        const uint4* Ag = (const uint4*)(g_x16 + (size_t)n0 * 1024);
        const uint4* Bg = (const uint4*)(g_w16 + (size_t)j0 * 1024);

        uint4 pa[4], pb[2];
        #pragma unroll
        for (int q = 0; q < 4; q++) { int f = q*256+t; pa[q] = Ag[(size_t)(f>>3)*128 + (f&7)]; }
        #pragma unroll
        for (int q = 0; q < 2; q++) { int f = q*256+t; pb[q] = Bg[(size_t)(f>>3)*128 + (f&7)]; }

        for (int c = 0; c < 16; c++) {
            __syncthreads();
            #pragma unroll
            for (int q = 0; q < 4; q++) { int f = q*256+t; *(uint4*)((char*)As + (f>>3)*144 + (f&7)*16) = pa[q]; }
            #pragma unroll
            for (int q = 0; q < 2; q++) { int f = q*256+t; *(uint4*)((char*)Bs + (f>>3)*144 + (f&7)*16) = pb[q]; }
            __syncthreads();
            if (c < 15) {
                #pragma unroll
                for (int q = 0; q < 4; q++) { int f = q*256+t; pa[q] = Ag[(size_t)(f>>3)*128 + (c+1)*8 + (f&7)]; }
                #pragma unroll
                for (int q = 0; q < 2; q++) { int f = q*256+t; pb[q] = Bg[(size_t)(f>>3)*128 + (c+1)*8 + (f&7)]; }
            }
            const uint32_t* Aw = (const uint32_t*)As;
            #pragma unroll
            for (int ks = 0; ks < 4; ks++) {
                uint32_t a[4];
                a[0] = Aw[(16*w + g)     * 36 + ks*8 + i];
                a[1] = Aw[(16*w + g + 8) * 36 + ks*8 + i];
                a[2] = Aw[(16*w + g)     * 36 + ks*8 + 4 + i];
                a[3] = Aw[(16*w + g + 8) * 36 + ks*8 + 4 + i];
                #pragma unroll
                for (int nb = 0; nb < 8; nb++) {
                    const char* br = (const char*)Bs + (nb*8 + g)*144 + i*4 + ks*32;
                    uint32_t b0 = *(const uint32_t*)br;
                    uint32_t b1 = *(const uint32_t*)(br + 16);
                    mma_f16(acc[nb], a, b0, b1);
                }
            }
        }
        const int r0 = n0 + 16*w + g;
        #pragma unroll
        for (int nb = 0; nb < 8; nb++) {
            int col = j0 + nb*8 + 2*i;
            float2 bv = *(const float2*)(qkv_b + col);
            float2 w0 = make_float2(acc[nb][0] + bv.x, acc[nb][1] + bv.y);
            float2 w1 = make_float2(acc[nb][2] + bv.x, acc[nb][3] + bv.y);
            const int sec = col >> 10;
            const int h = (col >> 6) & 15, d = col & 63;
            if (sec == 0) {
                *(float2*)(g_q + (size_t)((h << 10) + r0) * 64 + d)     = w0;
                *(float2*)(g_q + (size_t)((h << 10) + r0 + 8) * 64 + d) = w1;
            } else if (sec == 1) {
                *(float2*)(g_kn + (size_t)((h << 10) + r0) * 64 + d)     = w0;
                *(float2*)(g_kn + (size_t)((h << 10) + r0 + 8) * 64 + d) = w1;
                // f16 K rows (tok = 4096 + r0)
                uint32_t* kb0 = (uint32_t*)(g_kb + ((size_t)h * TTOT + TPAST + r0) * 64 + d);
                uint32_t* kb1 = (uint32_t*)(g_kb + ((size_t)h * TTOT + TPAST + r0 + 8) * 64 + d);
                *kb0 = packh(w0.x, w0.y);
                *kb1 = packh(w1.x, w1.y);
            } else {
                *(float2*)(g_vn + (size_t)((h << 10) + r0) * 64 + d)     = w0;
                *(float2*)(g_vn + (size_t)((h << 10) + r0 + 8) * 64 + d) = w1;
                // f16 V^T columns (tok = 4096 + r0), scalar stores
                __half* vt = g_vtb + (size_t)(h * 64 + d) * TTOT + TPAST;
                vt[r0]              = __float2half_rn(w0.x);
                vt[r0 + 8]          = __float2half_rn(w1.x);
                vt += TTOT;
                vt[r0]              = __float2half_rn(w0.y);
                vt[r0 + 8]          = __float2half_rn(w1.y);
            }
        }
    } else if (bx < 896) {     // ---------- conv_k past ----------
        const int idx = bx - 384;
        const int h = idx >> 5, t0 = (idx & 31) * 128;
        const float* src = pk + ((size_t)h * TPAST + t0) * 64;
        uint32_t* dst = reinterpret_cast<uint32_t*>(g_kb + ((size_t)h * TTOT + t0) * 64);
        #pragma unroll
        for (int q = 0; q < 8; q++) {
            int f = q * 256 + t;
            float4 v = *(const float4*)(src + (size_t)f * 4);
            dst[2*f]   = packh(v.x, v.y);
            dst[2*f+1] = packh(v.z, v.w);
        }
    } else if (bx < 1920) {    // ---------- conv_vt past ----------
        float (*ts)[65] = (float(*)[65])shm;
        const int idx = bx - 896;
        const int h = idx >> 6, t0 = (idx & 63) * 64;
        const float* src = pv + ((size_t)h * TPAST + t0) * 64;
        #pragma unroll
        for (int q = 0; q < 4; q++) {
            int f = q * 256 + t;
            int tok = f >> 4, d4 = (f & 15) * 4;
            float4 v = *(const float4*)(src + (size_t)tok * 64 + d4);
            ts[tok][d4+0] = v.x; ts[tok][d4+1] = v.y; ts[tok][d4+2] = v.z; ts[tok][d4+3] = v.w;
        }
        __syncthreads();
        const int d = t >> 2, c0 = (t & 3) * 16;
        uint32_t* orow = reinterpret_cast<uint32_t*>(g_vtb + ((size_t)h * 64 + d) * TTOT + t0);
        #pragma unroll
        for (int k = 0; k < 8; k++) {
            int tok = c0 + 2 * k;
            orow[c0/2 + k] = packh(ts[tok][d], ts[tok+1][d]);
        }
    } else {                   // ---------- scores ----------
        float* m = (float*)shm;
        const int idx = bx - 1920;
        const int h = idx / 12, pblk = idx % 12;
        if (t < 64) {
            float a = 0.0f;
            #pragma unroll
            for (int hh = 0; hh < 16; hh++) a += g_mm[hh * 64 + t];
            m[t] = a * (1.0f / (69.0f * 16.0f));
        }
        __syncthreads();
        const int p = pblk * 256 + t;
        const float* kr = pk + (size_t)(h * TPAST + 1024 + p) * 64;
        float acc = 0.0f;
        #pragma unroll
        for (int d = 0; d < 64; d += 4) {
            float4 v = *(const float4*)(kr + d);
            acc += m[d] * v.x + m[d+1] * v.y + m[d+2] * v.z + m[d+3] * v.w;
        }
        g_sp[h * 3072 + p] = acc;
    }
}

// ---------------- f16 tensor-core GEMM (proj only, mode-0 linear) --------
__global__ void __launch_bounds__(256) gemm_h16(
    const __half* __restrict__ A, const __half* __restrict__ B,
    const float* __restrict__ bias, float* __restrict__ C)
{
    __shared__ __half As[128 * 72];
    __shared__ __half Bs[64 * 72];
    const int t = threadIdx.x, lane = t & 31, w = t >> 5;
    const int j0 = blockIdx.x * 64, n0 = blockIdx.y * 128;
    const int g = lane >> 2, i = lane & 3;
    float acc[8][4] = {};
    const uint4* Ag = (const uint4*)(A + (size_t)n0 * 1024);
    const uint4* Bg = (const uint4*)(B + (size_t)j0 * 1024);

    uint4 pa[4], pb[2];
    #pragma unroll
    for (int q = 0; q < 4; q++) { int f = q*256+t; pa[q] = Ag[(size_t)(f>>3)*128 + (f&7)]; }
    #pragma unroll
    for (int q = 0; q < 2; q++) { int f = q*256+t; pb[q] = Bg[(size_t)(f>>3)*128 + (f&7)]; }

    for (int c = 0; c < 16; c++) {
        __syncthreads();
        #pragma unroll
        for (int q = 0; q < 4; q++) { int f = q*256+t; *(uint4*)((char*)As + (f>>3)*144 + (f&7)*16) = pa[q]; }
        #pragma unroll
        for (int q = 0; q < 2; q++) { int f = q*256+t; *(uint4*)((char*)Bs + (f>>3)*144 + (f&7)*16) = pb[q]; }
        __syncthreads();
        if (c < 15) {
            #pragma unroll
            for (int q = 0; q < 4; q++) { int f = q*256+t; pa[q] = Ag[(size_t)(f>>3)*128 + (c+1)*8 + (f&7)]; }
            #pragma unroll
            for (int q = 0; q < 2; q++) { int f = q*256+t; pb[q] = Bg[(size_t)(f>>3)*128 + (c+1)*8 + (f&7)]; }
        }
        const uint32_t* Aw = (const uint32_t*)As;
        #pragma unroll
        for (int ks = 0; ks < 4; ks++) {
            uint32_t a[4];
            a[0] = Aw[(16*w + g)     * 36 + ks*8 + i];
            a[1] = Aw[(16*w + g + 8) * 36 + ks*8 + i];
            a[2] = Aw[(16*w + g)     * 36 + ks*8 + 4 + i];
            a[3] = Aw[(16*w + g + 8) * 36 + ks*8 + 4 + i];
            #pragma unroll
            for (int nb = 0; nb < 8; nb++) {
                const char* br = (const char*)Bs + (nb*8 + g)*144 + i*4 + ks*32;
                uint32_t b0 = *(const uint32_t*)br;
                uint32_t b1 = *(const uint32_t*)(br + 16);
                mma_f16(acc[nb], a, b0, b1);
            }
        }
    }
    const int r0 = n0 + 16*w + g;
    #pragma unroll
    for (int nb = 0; nb < 8; nb++) {
        int col = j0 + nb*8 + 2*i;
        float2 bv = *(const float2*)(bias + col);
        *(float2*)(C + (size_t)r0 * 1024 + col) =
            make_float2(acc[nb][0] + bv.x, acc[nb][1] + bv.y);
        *(float2*)(C + (size_t)(r0 + 8) * 1024 + col) =
            make_float2(acc[nb][2] + bv.x, acc[nb][3] + bv.y);
    }
}

// ---- scores head-reduce + exact top-2048 radix select (fused) ----
__device__ __forceinline__ unsigned long long score_key(float s, int p) {
    unsigned u = __float_as_uint(s);
    u = (u & 0x80000000u) ? ~u : (u | 0x80000000u);
    return ((unsigned long long)u << 32) | (unsigned)(0xFFFFFFFFu - p);
}

__global__ void select_topk() {
    __shared__ int cnt[64];
    __shared__ int scan[1024];
    const int t = threadIdx.x, lid = t & 31;
    unsigned long long k[3];
    #pragma unroll
    for (int q = 0; q < 3; q++) {
        int p = t * 3 + q;
        float a = 0.0f;
        #pragma unroll
        for (int h = 0; h < 16; h++) a += g_sp[h * 3072 + p];
        k[q] = score_key(a * (1.0f / 16.0f), p);
    }
    if (t < 64) cnt[t] = 0;
    __syncthreads();
    unsigned long long prefix = 0;
    for (int b = 63; b >= 0; b--) {
        unsigned long long cand = prefix | (1ULL << b);
        int c = (int)(k[0] >= cand) + (int)(k[1] >= cand) + (int)(k[2] >= cand);
        #pragma unroll
        for (int o = 16; o; o >>= 1) c += __shfl_xor_sync(0xffffffffu, c, o);
        if (lid == 0) atomicAdd(&cnt[b], c);
        __syncthreads();
        if (cnt[b] >= KEEPM) prefix = cand;
    }
    bool kp[3]; int c2 = 0;
    #pragma unroll
    for (int q = 0; q < 3; q++) { kp[q] = (k[q] >= prefix); c2 += kp[q] ? 1 : 0; }
    scan[t] = c2;
    __syncthreads();
    for (int off = 1; off < 1024; off <<= 1) {
        int v = (t >= off) ? scan[t - off] : 0;
        __syncthreads();
        scan[t] += v;
        __syncthreads();
    }
    int pos = scan[t] - c2;
    #pragma unroll
    for (int q = 0; q < 3; q++)
        if (kp[q]) g_keep[pos++] = 1024 + t * 3 + q;
}

// ---------------- attention + gather fused ----------------
// grid (8,24) x 512. by<16: attn (h=by). by>=16: gather role.
__global__ void __launch_bounds__(512, 1)
attn_mma(const __half* __restrict__ kb, const __half* __restrict__ vtb,
         const float* __restrict__ pk, const float* __restrict__ pv,
         float* __restrict__ nk, float* __restrict__ nv) {
    extern __shared__ char sm[];
    const int t = threadIdx.x, lane = t & 31, w = t >> 5;

    if (blockIdx.y >= 16) {      // ---- gather role ----
        const int h = (blockIdx.y - 16) * 2 + (blockIdx.x >> 2);
        const int rc = blockIdx.x & 3;
        const int d4 = (t & 15) * 4;
        const int rbase = rc * 1024 + (t >> 4);
        #pragma unroll 4
        for (int j = 0; j < 32; j++) {
            const int r = rbase + j * 32;
            const int idx = (r < 1024) ? r : ((r < 3072) ? g_keep[r - 1024] : r + 1024);
            const float* ks; const float* vs;
            if (idx < TPAST) {
                ks = pk + (size_t)(h * TPAST + idx) * 64;
                vs = pv + (size_t)(h * TPAST + idx) * 64;
            } else {
                ks = g_kn + (size_t)((h << 10) + (idx - TPAST)) * 64;
                vs = g_vn + (size_t)((h << 10) + (idx - TPAST)) * 64;
            }
            const size_t rowid = (size_t)(h << 12) + r;
            *(float4*)(nk + rowid * 64 + d4) = *(const float4*)(ks + d4);
            *(float4*)(nv + rowid * 64 + d4) = *(const float4*)(vs + d4);
        }
        return;
    }

    // ---- attention role ----
    const int wg = w >> 3, wl = w & 7, tl = t & 255;
    const int h = blockIdx.y, n0 = blockIdx.x * 128;
    const int g = lane >> 2, i = lane & 3;
    const uint32_t smb = (uint32_t)__cvta_generic_to_shared(sm);
    const int base = wg * 2 * BUFB;
    const int barid = 1 + wg;

    #pragma unroll
    for (int bb = 0; bb < 2; bb++) {
        char* vt = sm + base + bb * BUFB + KSB;
        for (int f = tl; f < 1024; f += 256) {
            int r = f >> 7, c = f & 127;
            *(__half*)(vt + (64 + r) * 272 + c * 2) =
                (r == 0) ? __float2half(1.0f) : __float2half(0.0f);
        }
    }

    // Q fragments, pre-scaled into exp2 domain (SCALE * log2 e)
    uint32_t qa[4][4];
    {
        const float* qb = g_q + (size_t)((h << 10) + n0 + 16 * wl) * 64;
        #pragma unroll
        for (int ks = 0; ks < 4; ks++) {
            float2 x0 = *(const float2*)(qb + g * 64 + 16 * ks + 2 * i);
            float2 x1 = *(const float2*)(qb + g * 64 + 16 * ks + 8 + 2 * i);
            float2 x2 = *(const float2*)(qb + (g + 8) * 64 + 16 * ks + 2 * i);
            float2 x3 = *(const float2*)(qb + (g + 8) * 64 + 16 * ks + 8 + 2 * i);
            qa[ks][0] = packh(x0.x * SC2, x0.y * SC2);
            qa[ks][1] = packh(x2.x * SC2, x2.y * SC2);
            qa[ks][2] = packh(x1.x * SC2, x1.y * SC2);
            qa[ks][3] = packh(x3.x * SC2, x3.y * SC2);
        }
    }

    const char* kbh = (const char*)(kb + (size_t)h * TTOT * 64);
    const char* vth = (const char*)(vtb + (size_t)h * 64 * TTOT);

    float o[9][4];
    #pragma unroll
    for (int nd = 0; nd < 9; nd++)
        #pragma unroll
        for (int c = 0; c < 4; c++) o[nd][c] = 0.0f;

    auto stage = [&](int kt, int bi) {
        const char* ks = kbh + (size_t)kt * 16384;
        uint32_t kd = smb + base + bi * BUFB;
        #pragma unroll
        for (int q = 0; q < 4; q++) {
            int f = q * 256 + tl, tok = f >> 3, dc = f & 7;
            cp16(kd + tok * 144 + dc * 16, ks + tok * 128 + dc * 16);
        }
        uint32_t vd = kd + KSB;
        #pragma unroll
        for (int q = 0; q < 4; q++) {
            int f = q * 256 + tl, dd = f >> 4, c = f & 15;
            cp16(vd + dd * 272 + c * 16, vth + (size_t)dd * (TTOT * 2) + kt * 256 + c * 16);
        }
        asm volatile("cp.async.commit_group;" ::: "memory");
    };

    stage(wg, 0);
    for (int step = 0; step < 20; step++) {
        asm volatile("cp.async.wait_group 0;" ::: "memory");
        asm volatile("bar.sync %0, 256;" :: "r"(barid) : "memory");
        if (step < 19) stage(2 * (step + 1) + wg, (step + 1) & 1);
        const char* Ksb = sm + base + (step & 1) * BUFB;
        const char* VTb = Ksb + KSB;
        #pragma unroll
        for (int half = 0; half < 2; half++) {
            float s[8][4];
            #pragma unroll
            for (int nb = 0; nb < 8; nb++) {
                s[nb][0] = s[nb][1] = s[nb][2] = s[nb][3] = 0.0f;
                const char* kr = Ksb + ((half * 8 + nb) * 8 + g) * 144 + i * 4;
                #pragma unroll
                for (int ks = 0; ks < 4; ks++) {
                    uint32_t b0 = *(const uint32_t*)(kr + ks * 32);
                    uint32_t b1 = *(const uint32_t*)(kr + ks * 32 + 16);
                    mma_f16(s[nb], qa[ks], b0, b1);
                }
            }
            #pragma unroll
            for (int ks = 0; ks < 4; ks++) {
                uint32_t pa[4];
                pa[0] = expack(s[2*ks][0],   s[2*ks][1]);
                pa[1] = expack(s[2*ks][2],   s[2*ks][3]);
                pa[2] = expack(s[2*ks+1][0], s[2*ks+1][1]);
                pa[3] = expack(s[2*ks+1][2], s[2*ks+1][3]);
                const char* vr = VTb + g * 272 + i * 4 + (half * 4 + ks) * 32;
                #pragma unroll
                for (int nd = 0; nd < 9; nd++) {
                    uint32_t b0 = *(const uint32_t*)(vr + nd * 8 * 272);
                    uint32_t b1 = *(const uint32_t*)(vr + nd * 8 * 272 + 16);
                    mma_f16(o[nd], pa, b0, b1);
                }
            }
        }
    }

    __syncthreads();
    float* ms = (float*)sm;
    const int slot = (wl * 32 + lane) * 36;
    if (wg == 1) {
        #pragma unroll
        for (int nd = 0; nd < 9; nd++)
            #pragma unroll
            for (int c = 0; c < 4; c++) ms[slot + nd * 4 + c] = o[nd][c];
    }
    __syncthreads();
    if (wg == 0) {
        #pragma unroll
        for (int nd = 0; nd < 9; nd++)
            #pragma unroll
            for (int c = 0; c < 4; c++) o[nd][c] += ms[slot + nd * 4 + c];
        float lpg  = __shfl_sync(0xffffffffu, o[8][0], lane & ~3);
        float lpg8 = __shfl_sync(0xffffffffu, o[8][2], lane & ~3);
        float invg = 1.0f / lpg, inv8 = 1.0f / lpg8;
        const int r0 = n0 + 16 * wl + g;
        uint32_t* ob = (uint32_t*)(g_o16 + (size_t)r0 * DIMc + (h << 6) + 2 * i);
        #pragma unroll
        for (int nd = 0; nd < 8; nd++) {
            ob[nd * 4]                  = packh(o[nd][0] * invg, o[nd][1] * invg);
            ob[(8 * DIMc) / 2 + nd * 4] = packh(o[nd][2] * inv8, o[nd][3] * inv8);
        }
    }
}

// ---------------- launch ----------------
extern "C" void kernel_launch(void* const* d_in, const int* in_sizes, int n_in,
                              void* d_out, int out_size) {
    const float* x      = (const float*)d_in[0];
    const float* past_k = (const float*)d_in[1];
    const float* past_v = (const float*)d_in[2];
    const float* qkv_w  = (const float*)d_in[3];
    const float* qkv_b  = (const float*)d_in[4];
    const float* proj_w = (const float*)d_in[5];
    const float* proj_b = (const float*)d_in[6];

    float* out = (float*)d_out;
    float* nk  = out + (size_t)Nq * DIMc;
    float* nv  = nk + (size_t)Hh * 4096 * 64;

    __half *kb, *vtb, *pw16, *o16;
    cudaGetSymbolAddress((void**)&kb,   g_kb);
    cudaGetSymbolAddress((void**)&vtb,  g_vtb);
    cudaGetSymbolAddress((void**)&pw16, g_pw16);
    cudaGetSymbolAddress((void**)&o16,  g_o16);

    cudaFuncSetAttribute(attn_mma, cudaFuncAttributeMaxDynamicSharedMemorySize, ATTN_SMEM);

    stage1<<<5376, 256>>>(x, qkv_w, proj_w);
    qm<<<64, 256>>>(qkv_w, qkv_b);
    mega<<<2112, 256>>>(qkv_b, past_k, past_v);
    select_topk<<<1, 1024>>>();
    attn_mma<<<dim3(8, 24), 512, ATTN_SMEM>>>(kb, vtb, past_k, past_v, nk, nv);
    gemm_h16<<<dim3(16, 8), 256>>>(o16, pw16, proj_b, out);
}

// round 17
// speedup vs baseline: 1.0887x; 1.0887x over previous
#include <cuda_runtime.h>
#include <cuda_bf16.h>
#include <cuda_fp16.h>
#include <cstdint>

#define Hh    16
#define Dd    64
#define Nq    1024
#define TPAST 4096
#define TTOT  5120
#define DIMc  1024
#define MID   3072
#define KEEPM 2048
#define SC2   0.1803368801111157f   // 0.125 * log2(e): exp2-domain Q scale

#define KSB   18432            // K tile bytes (128 rows x 144B)
#define BUFB  38016            // K tile + V tile (72 x 272B)
#define ATTN_SMEM (4 * BUFB)   // 2 warp-groups x 2 buffers

// ---------------- device scratch ----------------
__device__ float g_q [Hh*Nq*Dd];
__device__ float g_kn[Hh*Nq*Dd];
__device__ float g_vn[Hh*Nq*Dd];
__device__ float g_xp[64*1024];
__device__ float g_mm[1024];
__device__ float g_sp[16*3072];
__device__ int   g_keep[KEEPM];
__device__ __half g_kb  [Hh*TTOT*Dd];   // K f16 [h][tok][d]
__device__ __half g_vtb [Hh*Dd*TTOT];   // V^T f16 [h][d][tok]
__device__ __half g_x16 [Nq*DIMc];
__device__ __half g_w16 [3072*DIMc];
__device__ __half g_pw16[DIMc*DIMc];
__device__ __half g_o16 [Nq*DIMc];      // attn out, f16 (written by attn epilogue)

// ---------------- helpers ----------------
__device__ __forceinline__ void mma_f16(float* d, const uint32_t* a, uint32_t b0, uint32_t b1) {
    asm volatile("mma.sync.aligned.m16n8k16.row.col.f32.f16.f16.f32 "
        "{%0,%1,%2,%3}, {%4,%5,%6,%7}, {%8,%9}, {%0,%1,%2,%3};"
        : "+f"(d[0]), "+f"(d[1]), "+f"(d[2]), "+f"(d[3])
        : "r"(a[0]), "r"(a[1]), "r"(a[2]), "r"(a[3]), "r"(b0), "r"(b1));
}
// exp2-domain weights: inputs pre-scaled by log2(e)
__device__ __forceinline__ uint32_t expack(float x, float y) {
    __half2 p = __floats2half2_rn(exp2f(x), exp2f(y));
    return *reinterpret_cast<uint32_t*>(&p);
}
__device__ __forceinline__ uint32_t packh(float a, float b) {
    __half2 t = __floats2half2_rn(a, b);
    return *reinterpret_cast<uint32_t*>(&t);
}
__device__ __forceinline__ void cp16(uint32_t dst, const void* src) {
    asm volatile("cp.async.cg.shared.global [%0], [%1], 16;" :: "r"(dst), "l"(src) : "memory");
}
__device__ __forceinline__ void conv_range(const float* __restrict__ s, __half* __restrict__ d, int f) {
    float4 v = *(const float4*)(s + (size_t)f * 4);
    *(uint2*)((char*)d + (size_t)f * 8) = make_uint2(packh(v.x, v.y), packh(v.z, v.w));
}

// ---------------- stage1: all input conversions + xm partials ------------
__global__ void stage1(const float* __restrict__ x, const float* __restrict__ qkv_w,
                       const float* __restrict__ proj_w) {
    const int b = blockIdx.x, t = threadIdx.x;
    if (b < 1024) {
        conv_range(x, g_x16, b * 256 + t);
    } else if (b < 4096) {
        conv_range(qkv_w, g_w16, (b - 1024) * 256 + t);
    } else if (b < 5120) {
        conv_range(proj_w, g_pw16, (b - 4096) * 256 + t);
    } else {
        const int q = b - 5120;
        const int c = (q & 3) * 256 + t;
        const int r0 = (q >> 2) * 16;
        float acc = 0.0f;
        for (int r = r0; r < r0 + 16; r++) {
            float w = (r < 5) ? 1.0f : (r < 1013 ? (1.0f / 16.0f) : (1.0f / 11.0f));
            acc += w * x[(size_t)r * 1024 + c];
        }
        g_xp[(q >> 2) * 1024 + c] = acc;
    }
}

// ---------------- qm: xw reduce + Wq·xw -----------
__global__ void qm(const float* __restrict__ Wq, const float* __restrict__ qb) {
    __shared__ float red[256];
    __shared__ float xw[1024];
    const int t = threadIdx.x;
    for (int c = t; c < 1024; c += 256) {
        float a = 0.0f;
        #pragma unroll
        for (int i = 0; i < 64; i++) a += g_xp[i * 1024 + c];
        xw[c] = a;
    }
    __syncthreads();
    const int jl = t >> 4, part = t & 15;
    const int j = blockIdx.x * 16 + jl;
    const float* wr = Wq + (size_t)j * 1024 + part * 64;
    const float* xp = &xw[part * 64];
    float acc = 0.0f;
    #pragma unroll
    for (int cc = 0; cc < 64; cc += 4) {
        float4 v = *(const float4*)(wr + cc);
        acc += v.x * xp[cc] + v.y * xp[cc+1] + v.z * xp[cc+2] + v.w * xp[cc+3];
    }
    red[t] = acc;
    __syncthreads();
    if (part == 0) {
        float s = 0.0f;
        #pragma unroll
        for (int p = 0; p < 16; p++) s += red[jl * 16 + p];
        g_mm[j] = s + 69.0f * qb[j];
    }
}

// ---------------- mega: qkv GEMM + past-KV conversion + scores -----------
__global__ void __launch_bounds__(256) mega(
    const float* __restrict__ qkv_b,
    const float* __restrict__ pk, const float* __restrict__ pv)
{
    __shared__ char shm[27648];
    const int bx = blockIdx.x, t = threadIdx.x;

    if (bx < 384) {            // ---------- gemm role ----------
        __half* As = (__half*)shm;
        __half* Bs = (__half*)(shm + 18432);
        const int lane = t & 31, w = t >> 5;
        const int j0 = (bx >> 3) * 64, n0 = (bx & 7) * 128;
        const int g = lane >> 2, i = lane & 3;
        float acc[8][4] = {};
        const uint4* Ag = (const uint4*)(g_x16 + (size_t)n0 * 1024);
        const uint4* Bg = (const uint4*)(g_w16 + (size_t)j0 * 1024);

        uint4 pa[4], pb[2];
        #pragma unroll
        for (int q = 0; q < 4; q++) { int f = q*256+t; pa[q] = Ag[(size_t)(f>>3)*128 + (f&7)]; }
        #pragma unroll
        for (int q = 0; q < 2; q++) { int f = q*256+t; pb[q] = Bg[(size_t)(f>>3)*128 + (f&7)]; }

        for (int c = 0; c < 16; c++) {
            __syncthreads();
            #pragma unroll
            for (int q = 0; q < 4; q++) { int f = q*256+t; *(uint4*)((char*)As + (f>>3)*144 + (f&7)*16) = pa[q]; }
            #pragma unroll
            for (int q = 0; q < 2; q++) { int f = q*256+t; *(uint4*)((char*)Bs + (f>>3)*144 + (f&7)*16) = pb[q]; }
            __syncthreads();
            if (c < 15) {
                #pragma unroll
                for (int q = 0; q < 4; q++) { int f = q*256+t; pa[q] = Ag[(size_t)(f>>3)*128 + (c+1)*8 + (f&7)]; }
                #pragma unroll
                for (int q = 0; q < 2; q++) { int f = q*256+t; pb[q] = Bg[(size_t)(f>>3)*128 + (c+1)*8 + (f&7)]; }
            }
            const uint32_t* Aw = (const uint32_t*)As;
            #pragma unroll
            for (int ks = 0; ks < 4; ks++) {
                uint32_t a[4];
                a[0] = Aw[(16*w + g)     * 36 + ks*8 + i];
                a[1] = Aw[(16*w + g + 8) * 36 + ks*8 + i];
                a[2] = Aw[(16*w + g)     * 36 + ks*8 + 4 + i];
                a[3] = Aw[(16*w + g + 8) * 36 + ks*8 + 4 + i];
                #pragma unroll
                for (int nb = 0; nb < 8; nb++) {
                    const char* br = (const char*)Bs + (nb*8 + g)*144 + i*4 + ks*32;
                    uint32_t b0 = *(const uint32_t*)br;
                    uint32_t b1 = *(const uint32_t*)(br + 16);
                    mma_f16(acc[nb], a, b0, b1);
                }
            }
        }
        const int r0 = n0 + 16*w + g;
        #pragma unroll
        for (int nb = 0; nb < 8; nb++) {
            int col = j0 + nb*8 + 2*i;
            float2 bv = *(const float2*)(qkv_b + col);
            float2 w0 = make_float2(acc[nb][0] + bv.x, acc[nb][1] + bv.y);
            float2 w1 = make_float2(acc[nb][2] + bv.x, acc[nb][3] + bv.y);
            const int sec = col >> 10;
            const int h = (col >> 6) & 15, d = col & 63;
            if (sec == 0) {
                *(float2*)(g_q + (size_t)((h << 10) + r0) * 64 + d)     = w0;
                *(float2*)(g_q + (size_t)((h << 10) + r0 + 8) * 64 + d) = w1;
            } else if (sec == 1) {
                *(float2*)(g_kn + (size_t)((h << 10) + r0) * 64 + d)     = w0;
                *(float2*)(g_kn + (size_t)((h << 10) + r0 + 8) * 64 + d) = w1;
                uint32_t* kb0 = (uint32_t*)(g_kb + ((size_t)h * TTOT + TPAST + r0) * 64 + d);
                uint32_t* kb1 = (uint32_t*)(g_kb + ((size_t)h * TTOT + TPAST + r0 + 8) * 64 + d);
                *kb0 = packh(w0.x, w0.y);
                *kb1 = packh(w1.x, w1.y);
            } else {
                *(float2*)(g_vn + (size_t)((h << 10) + r0) * 64 + d)     = w0;
                *(float2*)(g_vn + (size_t)((h << 10) + r0 + 8) * 64 + d) = w1;
                __half* vt = g_vtb + (size_t)(h * 64 + d) * TTOT + TPAST;
                vt[r0]     = __float2half_rn(w0.x);
                vt[r0 + 8] = __float2half_rn(w1.x);
                vt += TTOT;
                vt[r0]     = __float2half_rn(w0.y);
                vt[r0 + 8] = __float2half_rn(w1.y);
            }
        }
    } else if (bx < 896) {     // ---------- conv_k past ----------
        const int idx = bx - 384;
        const int h = idx >> 5, t0 = (idx & 31) * 128;
        const float* src = pk + ((size_t)h * TPAST + t0) * 64;
        uint32_t* dst = reinterpret_cast<uint32_t*>(g_kb + ((size_t)h * TTOT + t0) * 64);
        #pragma unroll
        for (int q = 0; q < 8; q++) {
            int f = q * 256 + t;
            float4 v = *(const float4*)(src + (size_t)f * 4);
            dst[2*f]   = packh(v.x, v.y);
            dst[2*f+1] = packh(v.z, v.w);
        }
    } else if (bx < 1920) {    // ---------- conv_vt past ----------
        float (*ts)[65] = (float(*)[65])shm;
        const int idx = bx - 896;
        const int h = idx >> 6, t0 = (idx & 63) * 64;
        const float* src = pv + ((size_t)h * TPAST + t0) * 64;
        #pragma unroll
        for (int q = 0; q < 4; q++) {
            int f = q * 256 + t;
            int tok = f >> 4, d4 = (f & 15) * 4;
            float4 v = *(const float4*)(src + (size_t)tok * 64 + d4);
            ts[tok][d4+0] = v.x; ts[tok][d4+1] = v.y; ts[tok][d4+2] = v.z; ts[tok][d4+3] = v.w;
        }
        __syncthreads();
        const int d = t >> 2, c0 = (t & 3) * 16;
        uint32_t* orow = reinterpret_cast<uint32_t*>(g_vtb + ((size_t)h * 64 + d) * TTOT + t0);
        #pragma unroll
        for (int k = 0; k < 8; k++) {
            int tok = c0 + 2 * k;
            orow[c0/2 + k] = packh(ts[tok][d], ts[tok+1][d]);
        }
    } else {                   // ---------- scores ----------
        float* m = (float*)shm;
        const int idx = bx - 1920;
        const int h = idx / 12, pblk = idx % 12;
        if (t < 64) {
            float a = 0.0f;
            #pragma unroll
            for (int hh = 0; hh < 16; hh++) a += g_mm[hh * 64 + t];
            m[t] = a * (1.0f / (69.0f * 16.0f));
        }
        __syncthreads();
        const int p = pblk * 256 + t;
        const float* kr = pk + (size_t)(h * TPAST + 1024 + p) * 64;
        float acc = 0.0f;
        #pragma unroll
        for (int d = 0; d < 64; d += 4) {
            float4 v = *(const float4*)(kr + d);
            acc += m[d] * v.x + m[d+1] * v.y + m[d+2] * v.z + m[d+3] * v.w;
        }
        g_sp[h * 3072 + p] = acc;
    }
}

// ---------------- f16 tensor-core GEMM (proj only, mode-0 linear) --------
__global__ void __launch_bounds__(256) gemm_h16(
    const __half* __restrict__ A, const __half* __restrict__ B,
    const float* __restrict__ bias, float* __restrict__ C)
{
    __shared__ __half As[128 * 72];
    __shared__ __half Bs[64 * 72];
    const int t = threadIdx.x, lane = t & 31, w = t >> 5;
    const int j0 = blockIdx.x * 64, n0 = blockIdx.y * 128;
    const int g = lane >> 2, i = lane & 3;
    float acc[8][4] = {};
    const uint4* Ag = (const uint4*)(A + (size_t)n0 * 1024);
    const uint4* Bg = (const uint4*)(B + (size_t)j0 * 1024);

    uint4 pa[4], pb[2];
    #pragma unroll
    for (int q = 0; q < 4; q++) { int f = q*256+t; pa[q] = Ag[(size_t)(f>>3)*128 + (f&7)]; }
    #pragma unroll
    for (int q = 0; q < 2; q++) { int f = q*256+t; pb[q] = Bg[(size_t)(f>>3)*128 + (f&7)]; }

    for (int c = 0; c < 16; c++) {
        __syncthreads();
        #pragma unroll
        for (int q = 0; q < 4; q++) { int f = q*256+t; *(uint4*)((char*)As + (f>>3)*144 + (f&7)*16) = pa[q]; }
        #pragma unroll
        for (int q = 0; q < 2; q++) { int f = q*256+t; *(uint4*)((char*)Bs + (f>>3)*144 + (f&7)*16) = pb[q]; }
        __syncthreads();
        if (c < 15) {
            #pragma unroll
            for (int q = 0; q < 4; q++) { int f = q*256+t; pa[q] = Ag[(size_t)(f>>3)*128 + (c+1)*8 + (f&7)]; }
            #pragma unroll
            for (int q = 0; q < 2; q++) { int f = q*256+t; pb[q] = Bg[(size_t)(f>>3)*128 + (c+1)*8 + (f&7)]; }
        }
        const uint32_t* Aw = (const uint32_t*)As;
        #pragma unroll
        for (int ks = 0; ks < 4; ks++) {
            uint32_t a[4];
            a[0] = Aw[(16*w + g)     * 36 + ks*8 + i];
            a[1] = Aw[(16*w + g + 8) * 36 + ks*8 + i];
            a[2] = Aw[(16*w + g)     * 36 + ks*8 + 4 + i];
            a[3] = Aw[(16*w + g + 8) * 36 + ks*8 + 4 + i];
            #pragma unroll
            for (int nb = 0; nb < 8; nb++) {
                const char* br = (const char*)Bs + (nb*8 + g)*144 + i*4 + ks*32;
                uint32_t b0 = *(const uint32_t*)br;
                uint32_t b1 = *(const uint32_t*)(br + 16);
                mma_f16(acc[nb], a, b0, b1);
            }
        }
    }
    const int r0 = n0 + 16*w + g;
    #pragma unroll
    for (int nb = 0; nb < 8; nb++) {
        int col = j0 + nb*8 + 2*i;
        float2 bv = *(const float2*)(bias + col);
        *(float2*)(C + (size_t)r0 * 1024 + col) =
            make_float2(acc[nb][0] + bv.x, acc[nb][1] + bv.y);
        *(float2*)(C + (size_t)(r0 + 8) * 1024 + col) =
            make_float2(acc[nb][2] + bv.x, acc[nb][3] + bv.y);
    }
}

// ---- scores head-reduce + exact top-2048: 8-bit MSB radix select --------
__device__ __forceinline__ unsigned long long score_key(float s, int p) {
    unsigned u = __float_as_uint(s);
    u = (u & 0x80000000u) ? ~u : (u | 0x80000000u);
    return ((unsigned long long)u << 32) | (unsigned)(0xFFFFFFFFu - p);
}

__global__ void select_topk() {
    __shared__ int bins[256];
    __shared__ unsigned long long sh_prefix;
    __shared__ int sh_need;
    __shared__ int wsum[32];
    const int t = threadIdx.x, lane = t & 31, wid = t >> 5;
    unsigned long long k[3];
    #pragma unroll
    for (int q = 0; q < 3; q++) {
        int p = t * 3 + q;
        float a = 0.0f;
        #pragma unroll
        for (int h = 0; h < 16; h++) a += g_sp[h * 3072 + p];
        k[q] = score_key(a * (1.0f / 16.0f), p);
    }
    if (t == 0) { sh_prefix = 0ULL; sh_need = KEEPM; }

    // 8 passes, 8 bits each, MSB first. prefix accumulates the exact
    // 2048th-largest key (keys are unique by construction).
    for (int pass = 0; pass < 8; pass++) {
        const int shift = 56 - pass * 8;
        if (t < 256) bins[t] = 0;
        __syncthreads();
        const unsigned long long pref = sh_prefix;
        const int need = sh_need;
        #pragma unroll
        for (int q = 0; q < 3; q++) {
            bool active = (pass == 0) ||
                          ((k[q] >> (shift + 8)) == (pref >> (shift + 8)));
            if (active) atomicAdd(&bins[(int)((k[q] >> shift) & 255)], 1);
        }
        __syncthreads();
        if (t < 32) {
            int loc[8]; int lsum = 0;
            #pragma unroll
            for (int j = 0; j < 8; j++) { loc[j] = bins[t * 8 + j]; lsum += loc[j]; }
            // inclusive suffix sum over lanes (lane t gets sum of lanes >= t)
            int v = lsum;
            #pragma unroll
            for (int o = 1; o < 32; o <<= 1) {
                int u = __shfl_down_sync(0xffffffffu, v, o);
                if (t + o < 32) v += u;
            }
            int cum = v - lsum;   // count with digit > t*8+7
            #pragma unroll
            for (int j = 7; j >= 0; j--) {
                int nc = cum + loc[j];
                if (cum < need && need <= nc) {
                    sh_prefix = pref | ((unsigned long long)(t * 8 + j) << shift);
                    sh_need = need - cum;
                }
                cum = nc;
            }
        }
        __syncthreads();
    }
    const unsigned long long prefix = sh_prefix;

    // compaction in ascending index order: warp scan + cross-warp scan
    bool kp[3]; int c2 = 0;
    #pragma unroll
    for (int q = 0; q < 3; q++) { kp[q] = (k[q] >= prefix); c2 += kp[q] ? 1 : 0; }
    int v = c2;
    #pragma unroll
    for (int o = 1; o < 32; o <<= 1) {
        int u = __shfl_up_sync(0xffffffffu, v, o);
        if (lane >= o) v += u;
    }
    if (lane == 31) wsum[wid] = v;
    __syncthreads();
    if (t < 32) {
        int s = wsum[t];
        #pragma unroll
        for (int o = 1; o < 32; o <<= 1) {
            int u = __shfl_up_sync(0xffffffffu, s, o);
            if (t >= o) s += u;
        }
        wsum[t] = s;
    }
    __syncthreads();
    int pos = ((wid > 0) ? wsum[wid - 1] : 0) + v - c2;
    #pragma unroll
    for (int q = 0; q < 3; q++)
        if (kp[q]) g_keep[pos++] = 1024 + t * 3 + q;
}

// ---------------- attention + gather fused ----------------
// grid (8,24) x 512. by<16: attn (h=by). by>=16: gather role.
__global__ void __launch_bounds__(512, 1)
attn_mma(const __half* __restrict__ kb, const __half* __restrict__ vtb,
         const float* __restrict__ pk, const float* __restrict__ pv,
         float* __restrict__ nk, float* __restrict__ nv) {
    extern __shared__ char sm[];
    const int t = threadIdx.x, lane = t & 31, w = t >> 5;

    if (blockIdx.y >= 16) {      // ---- gather role ----
        const int h = (blockIdx.y - 16) * 2 + (blockIdx.x >> 2);
        const int rc = blockIdx.x & 3;
        const int d4 = (t & 15) * 4;
        const int rbase = rc * 1024 + (t >> 4);
        #pragma unroll 4
        for (int j = 0; j < 32; j++) {
            const int r = rbase + j * 32;
            const int idx = (r < 1024) ? r : ((r < 3072) ? g_keep[r - 1024] : r + 1024);
            const float* ks; const float* vs;
            if (idx < TPAST) {
                ks = pk + (size_t)(h * TPAST + idx) * 64;
                vs = pv + (size_t)(h * TPAST + idx) * 64;
            } else {
                ks = g_kn + (size_t)((h << 10) + (idx - TPAST)) * 64;
                vs = g_vn + (size_t)((h << 10) + (idx - TPAST)) * 64;
            }
            const size_t rowid = (size_t)(h << 12) + r;
            *(float4*)(nk + rowid * 64 + d4) = *(const float4*)(ks + d4);
            *(float4*)(nv + rowid * 64 + d4) = *(const float4*)(vs + d4);
        }
        return;
    }

    // ---- attention role ----
    const int wg = w >> 3, wl = w & 7, tl = t & 255;
    const int h = blockIdx.y, n0 = blockIdx.x * 128;
    const int g = lane >> 2, i = lane & 3;
    const uint32_t smb = (uint32_t)__cvta_generic_to_shared(sm);
    const int base = wg * 2 * BUFB;
    const int barid = 1 + wg;

    #pragma unroll
    for (int bb = 0; bb < 2; bb++) {
        char* vt = sm + base + bb * BUFB + KSB;
        for (int f = tl; f < 1024; f += 256) {
            int r = f >> 7, c = f & 127;
            *(__half*)(vt + (64 + r) * 272 + c * 2) =
                (r == 0) ? __float2half(1.0f) : __float2half(0.0f);
        }
    }

    uint32_t qa[4][4];
    {
        const float* qb = g_q + (size_t)((h << 10) + n0 + 16 * wl) * 64;
        #pragma unroll
        for (int ks = 0; ks < 4; ks++) {
            float2 x0 = *(const float2*)(qb + g * 64 + 16 * ks + 2 * i);
            float2 x1 = *(const float2*)(qb + g * 64 + 16 * ks + 8 + 2 * i);
            float2 x2 = *(const float2*)(qb + (g + 8) * 64 + 16 * ks + 2 * i);
            float2 x3 = *(const float2*)(qb + (g + 8) * 64 + 16 * ks + 8 + 2 * i);
            qa[ks][0] = packh(x0.x * SC2, x0.y * SC2);
            qa[ks][1] = packh(x2.x * SC2, x2.y * SC2);
            qa[ks][2] = packh(x1.x * SC2, x1.y * SC2);
            qa[ks][3] = packh(x3.x * SC2, x3.y * SC2);
        }
    }

    const char* kbh = (const char*)(kb + (size_t)h * TTOT * 64);
    const char* vth = (const char*)(vtb + (size_t)h * 64 * TTOT);

    float o[9][4];
    #pragma unroll
    for (int nd = 0; nd < 9; nd++)
        #pragma unroll
        for (int c = 0; c < 4; c++) o[nd][c] = 0.0f;

    auto stage = [&](int kt, int bi) {
        const char* ks = kbh + (size_t)kt * 16384;
        uint32_t kd = smb + base + bi * BUFB;
        #pragma unroll
        for (int q = 0; q < 4; q++) {
            int f = q * 256 + tl, tok = f >> 3, dc = f & 7;
            cp16(kd + tok * 144 + dc * 16, ks + tok * 128 + dc * 16);
        }
        uint32_t vd = kd + KSB;
        #pragma unroll
        for (int q = 0; q < 4; q++) {
            int f = q * 256 + tl, dd = f >> 4, c = f & 15;
            cp16(vd + dd * 272 + c * 16, vth + (size_t)dd * (TTOT * 2) + kt * 256 + c * 16);
        }
        asm volatile("cp.async.commit_group;" ::: "memory");
    };

    stage(wg, 0);
    for (int step = 0; step < 20; step++) {
        asm volatile("cp.async.wait_group 0;" ::: "memory");
        asm volatile("bar.sync %0, 256;" :: "r"(barid) : "memory");
        if (step < 19) stage(2 * (step + 1) + wg, (step + 1) & 1);
        const char* Ksb = sm + base + (step & 1) * BUFB;
        const char* VTb = Ksb + KSB;
        #pragma unroll
        for (int half = 0; half < 2; half++) {
            float s[8][4];
            #pragma unroll
            for (int nb = 0; nb < 8; nb++) {
                s[nb][0] = s[nb][1] = s[nb][2] = s[nb][3] = 0.0f;
                const char* kr = Ksb + ((half * 8 + nb) * 8 + g) * 144 + i * 4;
                #pragma unroll
                for (int ks = 0; ks < 4; ks++) {
                    uint32_t b0 = *(const uint32_t*)(kr + ks * 32);
                    uint32_t b1 = *(const uint32_t*)(kr + ks * 32 + 16);
                    mma_f16(s[nb], qa[ks], b0, b1);
                }
            }
            #pragma unroll
            for (int ks = 0; ks < 4; ks++) {
                uint32_t pa[4];
                pa[0] = expack(s[2*ks][0],   s[2*ks][1]);
                pa[1] = expack(s[2*ks][2],   s[2*ks][3]);
                pa[2] = expack(s[2*ks+1][0], s[2*ks+1][1]);
                pa[3] = expack(s[2*ks+1][2], s[2*ks+1][3]);
                const char* vr = VTb + g * 272 + i * 4 + (half * 4 + ks) * 32;
                #pragma unroll
                for (int nd = 0; nd < 9; nd++) {
                    uint32_t b0 = *(const uint32_t*)(vr + nd * 8 * 272);
                    uint32_t b1 = *(const uint32_t*)(vr + nd * 8 * 272 + 16);
                    mma_f16(o[nd], pa, b0, b1);
                }
            }
        }
    }

    __syncthreads();
    float* ms = (float*)sm;
    const int slot = (wl * 32 + lane) * 36;
    if (wg == 1) {
        #pragma unroll
        for (int nd = 0; nd < 9; nd++)
            #pragma unroll
            for (int c = 0; c < 4; c++) ms[slot + nd * 4 + c] = o[nd][c];
    }
    __syncthreads();
    if (wg == 0) {
        #pragma unroll
        for (int nd = 0; nd < 9; nd++)
            #pragma unroll
            for (int c = 0; c < 4; c++) o[nd][c] += ms[slot + nd * 4 + c];
        float lpg  = __shfl_sync(0xffffffffu, o[8][0], lane & ~3);
        float lpg8 = __shfl_sync(0xffffffffu, o[8][2], lane & ~3);
        float invg = 1.0f / lpg, inv8 = 1.0f / lpg8;
        const int r0 = n0 + 16 * wl + g;
        uint32_t* ob = (uint32_t*)(g_o16 + (size_t)r0 * DIMc + (h << 6) + 2 * i);
        #pragma unroll
        for (int nd = 0; nd < 8; nd++) {
            ob[nd * 4]                  = packh(o[nd][0] * invg, o[nd][1] * invg);
            ob[(8 * DIMc) / 2 + nd * 4] = packh(o[nd][2] * inv8, o[nd][3] * inv8);
        }
    }
}

// ---------------- launch ----------------
extern "C" void kernel_launch(void* const* d_in, const int* in_sizes, int n_in,
                              void* d_out, int out_size) {
    const float* x      = (const float*)d_in[0];
    const float* past_k = (const float*)d_in[1];
    const float* past_v = (const float*)d_in[2];
    const float* qkv_w  = (const float*)d_in[3];
    const float* qkv_b  = (const float*)d_in[4];
    const float* proj_w = (const float*)d_in[5];
    const float* proj_b = (const float*)d_in[6];

    float* out = (float*)d_out;
    float* nk  = out + (size_t)Nq * DIMc;
    float* nv  = nk + (size_t)Hh * 4096 * 64;

    __half *kb, *vtb, *pw16, *o16;
    cudaGetSymbolAddress((void**)&kb,   g_kb);
    cudaGetSymbolAddress((void**)&vtb,  g_vtb);
    cudaGetSymbolAddress((void**)&pw16, g_pw16);
    cudaGetSymbolAddress((void**)&o16,  g_o16);

    cudaFuncSetAttribute(attn_mma, cudaFuncAttributeMaxDynamicSharedMemorySize, ATTN_SMEM);

    stage1<<<5376, 256>>>(x, qkv_w, proj_w);
    qm<<<64, 256>>>(qkv_w, qkv_b);
    mega<<<2112, 256>>>(qkv_b, past_k, past_v);
    select_topk<<<1, 1024>>>();
    attn_mma<<<dim3(8, 24), 512, ATTN_SMEM>>>(kb, vtb, past_k, past_v, nk, nv);
    gemm_h16<<<dim3(16, 8), 256>>>(o16, pw16, proj_b, out);
}